// round 2
// baseline (speedup 1.0000x reference)
#include <cuda_runtime.h>

// ---------------- problem constants ----------------
#define BATCH 512
#define NEQv  4096
#define XDIMv 6144
#define H1v   2048
#define H2v   2048
#define YDIMv 4096
#define NEDGE 32768

// ---------------- scratch (device globals; no runtime alloc) ----------------
__device__ __align__(256) float g_z0[BATCH * XDIMv];   // GCN output ++ x_g  [512,6144]
__device__ __align__(256) float g_z1[BATCH * H1v];     // layer1 out         [512,2048]
__device__ __align__(256) float g_z2[BATCH * H2v];     // layer2 out         [512,2048]
__device__ int   g_cnt[NEQv];                          // dst-degree counts
__device__ float g_acc[NEQv];                          // edge scatter accum

// ============================================================
// GCN kernels (tiny)
// ============================================================
__global__ void k_init() {
    int i = blockIdx.x * blockDim.x + threadIdx.x;
    if (i < NEQv) { g_cnt[i] = 0; g_acc[i] = 0.f; }
}

__global__ void k_count(const int* __restrict__ ei) {
    int e = blockIdx.x * blockDim.x + threadIdx.x;
    if (e < NEDGE) atomicAdd(&g_cnt[ei[NEDGE + e]], 1);
}

__global__ void k_scatter(const int* __restrict__ ei, const float* __restrict__ x,
                          const float* __restrict__ gw) {
    int e = blockIdx.x * blockDim.x + threadIdx.x;
    if (e >= NEDGE) return;
    int s = ei[e];            // src node id (< 4096, flattened space)
    int d = ei[NEDGE + e];    // dst node id (< 4096)
    float deg_s = 1.f + 512.f * (float)g_cnt[s];
    // xf[s] = x[s % 512][s / 512]
    float xw = gw[0] * x[(size_t)(s & 511) * XDIMv + (s >> 9)];
    atomicAdd(&g_acc[d], rsqrtf(deg_s) * xw);
}

__global__ void k_build_z(const float* __restrict__ x, const float* __restrict__ gw,
                          const float* __restrict__ gb) {
    int idx = blockIdx.x * blockDim.x + threadIdx.x;
    if (idx >= BATCH * XDIMv) return;
    int b = idx / XDIMv;
    int j = idx - b * XDIMv;
    float v = x[idx];
    float z;
    if (j >= NEQv) {
        z = v;                                   // x_g passthrough, no relu
    } else {
        float w  = gw[0];
        float xw = w * v;
        float out;
        if (j < 8) {                             // only flattened node ids < 4096 touched by edges
            int i = (j << 9) + b;                // i = j*512 + b < 4096
            float deg  = 1.f + 512.f * (float)g_cnt[i];
            out = xw / deg + 512.f * rsqrtf(deg) * g_acc[i] + gb[0];
        } else {
            out = xw + gb[0];                    // deg = 1 (self loop only)
        }
        z = fmaxf(out, 0.f);
    }
    g_z0[idx] = z;
}

// ============================================================
// GEMM: C[M,N] = act(A[M,K] @ W[K,N] + bias)
// split-tf32 (3-MMA) for fp32-grade accuracy on tensor cores
// ============================================================
#define BM 128
#define BN 64
#define BK 32
#define APITCH 36       // conflict-free: bank = (36*r + c) % 32 = lane
#define BPITCH 72       // conflict-free: bank = (8*row + col) % 32
#define STAGES 3
#define STAGE_F (BM * APITCH + BK * BPITCH)      // 6912 floats
#define GEMM_SMEM_BYTES (STAGES * STAGE_F * 4)   // 82944 bytes

__device__ __forceinline__ unsigned smem_u32(const void* p) {
    return (unsigned)__cvta_generic_to_shared(p);
}
__device__ __forceinline__ void cp16(void* dst, const void* src) {
    asm volatile("cp.async.ca.shared.global [%0], [%1], 16;\n"
                 :: "r"(smem_u32(dst)), "l"(src));
}
#define CP_COMMIT() asm volatile("cp.async.commit_group;\n")
#define CP_WAIT1()  asm volatile("cp.async.wait_group 1;\n")

#define MMA_TF32(C, A, B)                                                        \
    asm volatile("mma.sync.aligned.m16n8k8.row.col.f32.tf32.tf32.f32 "           \
                 "{%0,%1,%2,%3},{%4,%5,%6,%7},{%8,%9},{%0,%1,%2,%3};\n"          \
                 : "+f"((C)[0]), "+f"((C)[1]), "+f"((C)[2]), "+f"((C)[3])         \
                 : "r"((A)[0]), "r"((A)[1]), "r"((A)[2]), "r"((A)[3]),            \
                   "r"((B)[0]), "r"((B)[1]))

__device__ __forceinline__ void split_tf32(float v, unsigned& hi, unsigned& lo) {
    hi = __float_as_uint(v) & 0xFFFFE000u;          // RZ-truncated tf32 high part
    float l = v - __uint_as_float(hi);              // exact (Sterbenz)
    lo = __float_as_uint(l);                        // HW reads top 19 bits (RZ) — fine
}

template<int RELU>
__global__ void __launch_bounds__(256, 1) k_gemm(
    const float* __restrict__ A, const float* __restrict__ W,
    const float* __restrict__ bias, float* __restrict__ C,
    int M, int N, int K)
{
    extern __shared__ float smem[];
    const int tid  = threadIdx.x;
    const int lane = tid & 31;
    const int wid  = tid >> 5;
    const int wm   = wid & 3;        // 4 warps in M -> 32 rows each
    const int wn   = wid >> 2;       // 2 warps in N -> 32 cols each
    const int m0   = blockIdx.y * BM;
    const int n0   = blockIdx.x * BN;
    const int r    = lane >> 2;      // group id
    const int q    = lane & 3;       // thread-in-group

    float* As[STAGES]; float* Bs[STAGES];
#pragma unroll
    for (int s = 0; s < STAGES; s++) {
        As[s] = smem + s * STAGE_F;
        Bs[s] = smem + s * STAGE_F + BM * APITCH;
    }

    float c[2][4][4];
#pragma unroll
    for (int i = 0; i < 2; i++)
#pragma unroll
        for (int j = 0; j < 4; j++)
#pragma unroll
            for (int k = 0; k < 4; k++) c[i][j][k] = 0.f;

    const int kIters = K / BK;

    auto loadStage = [&](int it, int stg) {
        const int k0 = it * BK;
        float* as = As[stg];
#pragma unroll
        for (int t = 0; t < 4; t++) {             // A: 128x32 floats = 1024 x 16B
            int ch = tid + t * 256;
            int rr = ch >> 3, c4 = (ch & 7) << 2;
            cp16(&as[rr * APITCH + c4], &A[(size_t)(m0 + rr) * K + k0 + c4]);
        }
        float* bs = Bs[stg];
#pragma unroll
        for (int t = 0; t < 2; t++) {             // W: 32x64 floats = 512 x 16B
            int ch = tid + t * 256;
            int rr = ch >> 4, c4 = (ch & 15) << 2;
            cp16(&bs[rr * BPITCH + c4], &W[(size_t)(k0 + rr) * N + n0 + c4]);
        }
    };

    loadStage(0, 0); CP_COMMIT();
    loadStage(1, 1); CP_COMMIT();

    for (int it = 0; it < kIters; ++it) {
        CP_WAIT1();
        __syncthreads();
        if (it + 2 < kIters) loadStage(it + 2, (it + 2) % STAGES);
        CP_COMMIT();

        const float* as = As[it % STAGES];
        const float* bs = Bs[it % STAGES];

#pragma unroll
        for (int ks = 0; ks < 4; ks++) {
            const int k0 = ks * 8;
            unsigned ah[2][4], al[2][4], bh[4][2], bl[4][2];
#pragma unroll
            for (int mt = 0; mt < 2; mt++) {
                const float* ap = &as[(wm * 32 + mt * 16 + r) * APITCH + k0 + q];
                split_tf32(ap[0],              ah[mt][0], al[mt][0]);
                split_tf32(ap[8 * APITCH],     ah[mt][1], al[mt][1]);
                split_tf32(ap[4],              ah[mt][2], al[mt][2]);
                split_tf32(ap[8 * APITCH + 4], ah[mt][3], al[mt][3]);
            }
#pragma unroll
            for (int nt = 0; nt < 4; nt++) {
                const float* bp = &bs[(k0 + q) * BPITCH + wn * 32 + nt * 8 + r];
                split_tf32(bp[0],          bh[nt][0], bl[nt][0]);
                split_tf32(bp[4 * BPITCH], bh[nt][1], bl[nt][1]);
            }
#pragma unroll
            for (int mt = 0; mt < 2; mt++)
#pragma unroll
                for (int nt = 0; nt < 4; nt++) {
                    MMA_TF32(c[mt][nt], ah[mt], bh[nt]);
                    MMA_TF32(c[mt][nt], ah[mt], bl[nt]);
                    MMA_TF32(c[mt][nt], al[mt], bh[nt]);
                }
        }
    }

    // epilogue: bias + optional relu, float2 stores
#pragma unroll
    for (int mt = 0; mt < 2; mt++) {
#pragma unroll
        for (int nt = 0; nt < 4; nt++) {
            int row0 = m0 + wm * 32 + mt * 16 + r;
            int col0 = n0 + wn * 32 + nt * 8 + 2 * q;
            float bb0 = bias[col0], bb1 = bias[col0 + 1];
            float2 v0 = make_float2(c[mt][nt][0] + bb0, c[mt][nt][1] + bb1);
            float2 v1 = make_float2(c[mt][nt][2] + bb0, c[mt][nt][3] + bb1);
            if (RELU) {
                v0.x = fmaxf(v0.x, 0.f); v0.y = fmaxf(v0.y, 0.f);
                v1.x = fmaxf(v1.x, 0.f); v1.y = fmaxf(v1.y, 0.f);
            }
            *(float2*)&C[(size_t)row0 * N + col0]       = v0;
            *(float2*)&C[(size_t)(row0 + 8) * N + col0] = v1;
        }
    }
}

// ============================================================
// launch
// ============================================================
extern "C" void kernel_launch(void* const* d_in, const int* in_sizes, int n_in,
                              void* d_out, int out_size) {
    const float* x  = (const float*)d_in[0];
    const int*   ei = (const int*)  d_in[1];
    const float* gw = (const float*)d_in[2];
    const float* gb = (const float*)d_in[3];
    const float* W1 = (const float*)d_in[4];
    const float* b1 = (const float*)d_in[5];
    const float* W2 = (const float*)d_in[6];
    const float* b2 = (const float*)d_in[7];
    const float* W3 = (const float*)d_in[8];
    const float* b3 = (const float*)d_in[9];
    float* out = (float*)d_out;

    cudaFuncSetAttribute(k_gemm<1>, cudaFuncAttributeMaxDynamicSharedMemorySize, GEMM_SMEM_BYTES);
    cudaFuncSetAttribute(k_gemm<0>, cudaFuncAttributeMaxDynamicSharedMemorySize, GEMM_SMEM_BYTES);

    void *z0p, *z1p, *z2p;
    cudaGetSymbolAddress(&z0p, g_z0);
    cudaGetSymbolAddress(&z1p, g_z1);
    cudaGetSymbolAddress(&z2p, g_z2);
    float* z0 = (float*)z0p;
    float* z1 = (float*)z1p;
    float* z2 = (float*)z2p;

    // GCN
    k_init<<<NEQv / 256, 256>>>();
    k_count<<<NEDGE / 256, 256>>>(ei);
    k_scatter<<<NEDGE / 256, 256>>>(ei, x, gw);
    k_build_z<<<(BATCH * XDIMv) / 256, 256>>>(x, gw, gb);

    // MLP: z1 = relu(z0@W1+b1); z2 = relu(z1@W2+b2); out = z2@W3+b3
    dim3 g1(H1v / BN,   BATCH / BM);   // (32, 4)
    dim3 g2(H2v / BN,   BATCH / BM);   // (32, 4)
    dim3 g3(YDIMv / BN, BATCH / BM);   // (64, 4)
    k_gemm<1><<<g1, 256, GEMM_SMEM_BYTES>>>(z0, W1, b1, z1, BATCH, H1v,   XDIMv);
    k_gemm<1><<<g2, 256, GEMM_SMEM_BYTES>>>(z1, W2, b2, z2, BATCH, H2v,   H1v);
    k_gemm<0><<<g3, 256, GEMM_SMEM_BYTES>>>(z2, W3, b3, out, BATCH, YDIMv, H2v);
}

// round 6
// speedup vs baseline: 1.2485x; 1.2485x over previous
#include <cuda_runtime.h>
#include <cuda_bf16.h>
#include <cstdint>

// ---------------- problem constants ----------------
#define BATCH 512
#define NEQv  4096
#define XDIMv 6144
#define H1v   2048
#define H2v   2048
#define YDIMv 4096
#define NEDGE 32768

// ---------------- scratch (device globals; no runtime alloc) ----------------
__device__ __align__(256) float g_z0[BATCH * XDIMv];   // GCN output ++ x_g  [512,6144]
__device__ __align__(256) float g_z1[BATCH * H1v];     // layer1 out         [512,2048]
__device__ __align__(256) float g_z2[BATCH * H2v];     // layer2 out         [512,2048]
__device__ int   g_cnt[NEQv];
__device__ float g_acc[NEQv];

// ============================================================
// GCN kernels (verified passing in R1)
// ============================================================
__global__ void k_init() {
    int i = blockIdx.x * blockDim.x + threadIdx.x;
    if (i < NEQv) { g_cnt[i] = 0; g_acc[i] = 0.f; }
}

__global__ void k_count(const int* __restrict__ ei) {
    int e = blockIdx.x * blockDim.x + threadIdx.x;
    if (e < NEDGE) atomicAdd(&g_cnt[ei[NEDGE + e]], 1);
}

__global__ void k_scatter(const int* __restrict__ ei, const float* __restrict__ x,
                          const float* __restrict__ gw) {
    int e = blockIdx.x * blockDim.x + threadIdx.x;
    if (e >= NEDGE) return;
    int s = ei[e];
    int d = ei[NEDGE + e];
    float deg_s = 1.f + 512.f * (float)g_cnt[s];
    float xw = gw[0] * x[(size_t)(s & 511) * XDIMv + (s >> 9)];
    atomicAdd(&g_acc[d], rsqrtf(deg_s) * xw);
}

__global__ void k_build_z(const float* __restrict__ x, const float* __restrict__ gw,
                          const float* __restrict__ gb) {
    int idx = blockIdx.x * blockDim.x + threadIdx.x;
    if (idx >= BATCH * XDIMv) return;
    int b = idx / XDIMv;
    int j = idx - b * XDIMv;
    float v = x[idx];
    float z;
    if (j >= NEQv) {
        z = v;
    } else {
        float xw = gw[0] * v;
        float out;
        if (j < 8) {
            int i = (j << 9) + b;
            float deg = 1.f + 512.f * (float)g_cnt[i];
            out = xw / deg + 512.f * rsqrtf(deg) * g_acc[i] + gb[0];
        } else {
            out = xw + gb[0];
        }
        z = fmaxf(out, 0.f);
    }
    g_z0[idx] = z;
}

// ============================================================
// GEMM: C[M,N] = act(A[M,K] @ W[K,N] + bias)
// fp32 storage everywhere (R1-proven); in-register bf16 split feeding
// mma.m16n8k16.bf16 (3-term split: ah*bh + ah*bl + al*bh)
// ============================================================
#define BM 128
#define BN 64
#define BK 32
#define APITCH 40       // fp32/row; float2 frag loads conflict-free
#define BPITCH 68       // fp32/row; scalar frag loads conflict-free (banks 8q+r)
#define STAGES 3
#define STAGE_F (BM * APITCH + BK * BPITCH)      // 5120 + 2176 = 7296 floats
#define GEMM_SMEM_BYTES (STAGES * STAGE_F * 4)   // 87552 bytes

__device__ __forceinline__ unsigned smem_u32(const void* p) {
    return (unsigned)__cvta_generic_to_shared(p);
}
__device__ __forceinline__ void cp16(void* dst, const void* src) {
    asm volatile("cp.async.ca.shared.global [%0], [%1], 16;\n"
                 :: "r"(smem_u32(dst)), "l"(src));
}
#define CP_COMMIT() asm volatile("cp.async.commit_group;\n")
#define CP_WAIT1()  asm volatile("cp.async.wait_group 1;\n")

#define MMA_BF16(C, A, B)                                                        \
    asm volatile("mma.sync.aligned.m16n8k16.row.col.f32.bf16.bf16.f32 "          \
                 "{%0,%1,%2,%3},{%4,%5,%6,%7},{%8,%9},{%0,%1,%2,%3};\n"          \
                 : "+f"((C)[0]), "+f"((C)[1]), "+f"((C)[2]), "+f"((C)[3])         \
                 : "r"((A)[0]), "r"((A)[1]), "r"((A)[2]), "r"((A)[3]),            \
                   "r"((B)[0]), "r"((B)[1]))

// split f0,f1 into packed bf16x2 hi (truncated, 1 PRMT) + bf16x2 lo (RN residual)
__device__ __forceinline__ void packsplit(float f0, float f1, uint32_t& hi, uint32_t& lo) {
    uint32_t u0 = __float_as_uint(f0), u1 = __float_as_uint(f1);
    hi = __byte_perm(u0, u1, 0x7632);
    float l0 = f0 - __uint_as_float(u0 & 0xFFFF0000u);   // exact (Sterbenz)
    float l1 = f1 - __uint_as_float(u1 & 0xFFFF0000u);
    __nv_bfloat162 p = __floats2bfloat162_rn(l0, l1);    // x=l0 (low half), y=l1
    lo = *(uint32_t*)&p;
}

template<int RELU>
__global__ void __launch_bounds__(256, 1) k_gemm(
    const float* __restrict__ A, const float* __restrict__ W,
    const float* __restrict__ bias, float* __restrict__ C,
    int M, int N, int K)
{
    extern __shared__ float smem[];
    const int tid  = threadIdx.x;
    const int lane = tid & 31;
    const int wid  = tid >> 5;
    const int wm   = wid & 3;        // 4 warps in M -> 32 rows each
    const int wn   = wid >> 2;       // 2 warps in N -> 32 cols each
    const int m0   = blockIdx.y * BM;
    const int n0   = blockIdx.x * BN;
    const int r    = lane >> 2;      // 0..7
    const int q    = lane & 3;       // 0..3

    float* As[STAGES]; float* Bs[STAGES];
#pragma unroll
    for (int s = 0; s < STAGES; s++) {
        As[s] = smem + s * STAGE_F;
        Bs[s] = smem + s * STAGE_F + BM * APITCH;
    }

    float c[2][4][4];
#pragma unroll
    for (int i = 0; i < 2; i++)
#pragma unroll
        for (int j = 0; j < 4; j++)
#pragma unroll
            for (int k = 0; k < 4; k++) c[i][j][k] = 0.f;

    const int kIters = K / BK;

    auto loadStage = [&](int it, int stg) {
        const int k0 = it * BK;
        float* as = As[stg];
#pragma unroll
        for (int t = 0; t < 4; t++) {             // A: 128 rows x 8 chunks of 16B
            int id = tid + t * 256;
            int rr = id >> 3, ch = (id & 7) << 2;
            cp16(&as[rr * APITCH + ch], &A[(size_t)(m0 + rr) * K + k0 + ch]);
        }
        float* bs = Bs[stg];
#pragma unroll
        for (int t = 0; t < 2; t++) {             // B: 32 rows x 16 chunks of 16B
            int id = tid + t * 256;
            int rr = id >> 4, ch = (id & 15) << 2;
            cp16(&bs[rr * BPITCH + ch], &W[(size_t)(k0 + rr) * N + n0 + ch]);
        }
    };

    loadStage(0, 0); CP_COMMIT();
    loadStage(1, 1); CP_COMMIT();

    for (int it = 0; it < kIters; ++it) {
        CP_WAIT1();
        __syncthreads();
        if (it + 2 < kIters) loadStage(it + 2, (it + 2) % STAGES);
        CP_COMMIT();

        const float* as = As[it % STAGES];
        const float* bs = Bs[it % STAGES];

#pragma unroll
        for (int kk = 0; kk < BK; kk += 16) {
            uint32_t ah[2][4], al[2][4], bh[4][2], bl[4][2];
#pragma unroll
            for (int mt = 0; mt < 2; mt++) {
                const float* ap = &as[(wm * 32 + mt * 16 + r) * APITCH + kk + 2 * q];
                float2 p0 = *(const float2*)(ap);
                float2 p1 = *(const float2*)(ap + 8 * APITCH);
                float2 p2 = *(const float2*)(ap + 8);
                float2 p3 = *(const float2*)(ap + 8 * APITCH + 8);
                packsplit(p0.x, p0.y, ah[mt][0], al[mt][0]);
                packsplit(p1.x, p1.y, ah[mt][1], al[mt][1]);
                packsplit(p2.x, p2.y, ah[mt][2], al[mt][2]);
                packsplit(p3.x, p3.y, ah[mt][3], al[mt][3]);
            }
#pragma unroll
            for (int nt = 0; nt < 4; nt++) {
                const float* bp = &bs[(kk + 2 * q) * BPITCH + wn * 32 + nt * 8 + r];
                float f0 = bp[0];
                float f1 = bp[BPITCH];
                float f2 = bp[8 * BPITCH];
                float f3 = bp[9 * BPITCH];
                packsplit(f0, f1, bh[nt][0], bl[nt][0]);
                packsplit(f2, f3, bh[nt][1], bl[nt][1]);
            }
            // 3 split terms; each sweep = 8 independent accumulators (ILP)
#pragma unroll
            for (int mt = 0; mt < 2; mt++)
#pragma unroll
                for (int nt = 0; nt < 4; nt++)
                    MMA_BF16(c[mt][nt], ah[mt], bh[nt]);
#pragma unroll
            for (int mt = 0; mt < 2; mt++)
#pragma unroll
                for (int nt = 0; nt < 4; nt++)
                    MMA_BF16(c[mt][nt], ah[mt], bl[nt]);
#pragma unroll
            for (int mt = 0; mt < 2; mt++)
#pragma unroll
                for (int nt = 0; nt < 4; nt++)
                    MMA_BF16(c[mt][nt], al[mt], bh[nt]);
        }
    }

    // epilogue: bias + optional relu, float2 stores (R1-proven)
#pragma unroll
    for (int mt = 0; mt < 2; mt++) {
#pragma unroll
        for (int nt = 0; nt < 4; nt++) {
            int row0 = m0 + wm * 32 + mt * 16 + r;
            int col0 = n0 + wn * 32 + nt * 8 + 2 * q;
            float bb0 = bias[col0], bb1 = bias[col0 + 1];
            float2 v0 = make_float2(c[mt][nt][0] + bb0, c[mt][nt][1] + bb1);
            float2 v1 = make_float2(c[mt][nt][2] + bb0, c[mt][nt][3] + bb1);
            if (RELU) {
                v0.x = fmaxf(v0.x, 0.f); v0.y = fmaxf(v0.y, 0.f);
                v1.x = fmaxf(v1.x, 0.f); v1.y = fmaxf(v1.y, 0.f);
            }
            *(float2*)&C[(size_t)row0 * N + col0]       = v0;
            *(float2*)&C[(size_t)(row0 + 8) * N + col0] = v1;
        }
    }
}

// ============================================================
// launch
// ============================================================
extern "C" void kernel_launch(void* const* d_in, const int* in_sizes, int n_in,
                              void* d_out, int out_size) {
    const float* x  = (const float*)d_in[0];
    const int*   ei = (const int*)  d_in[1];
    const float* gw = (const float*)d_in[2];
    const float* gb = (const float*)d_in[3];
    const float* W1 = (const float*)d_in[4];
    const float* b1 = (const float*)d_in[5];
    const float* W2 = (const float*)d_in[6];
    const float* b2 = (const float*)d_in[7];
    const float* W3 = (const float*)d_in[8];
    const float* b3 = (const float*)d_in[9];
    float* out = (float*)d_out;

    cudaFuncSetAttribute(k_gemm<1>, cudaFuncAttributeMaxDynamicSharedMemorySize, GEMM_SMEM_BYTES);
    cudaFuncSetAttribute(k_gemm<0>, cudaFuncAttributeMaxDynamicSharedMemorySize, GEMM_SMEM_BYTES);

    void *z0p, *z1p, *z2p;
    cudaGetSymbolAddress(&z0p, g_z0);
    cudaGetSymbolAddress(&z1p, g_z1);
    cudaGetSymbolAddress(&z2p, g_z2);
    float* z0 = (float*)z0p;
    float* z1 = (float*)z1p;
    float* z2 = (float*)z2p;

    // GCN
    k_init<<<NEQv / 256, 256>>>();
    k_count<<<NEDGE / 256, 256>>>(ei);
    k_scatter<<<NEDGE / 256, 256>>>(ei, x, gw);
    k_build_z<<<(BATCH * XDIMv) / 256, 256>>>(x, gw, gb);

    // MLP
    dim3 g1(H1v / BN,   BATCH / BM);   // (32, 4)
    dim3 g2(H2v / BN,   BATCH / BM);   // (32, 4)
    dim3 g3(YDIMv / BN, BATCH / BM);   // (64, 4)
    k_gemm<1><<<g1, 256, GEMM_SMEM_BYTES>>>(z0, W1, b1, z1, BATCH, H1v,   XDIMv);
    k_gemm<1><<<g2, 256, GEMM_SMEM_BYTES>>>(z1, W2, b2, z2, BATCH, H2v,   H1v);
    k_gemm<0><<<g3, 256, GEMM_SMEM_BYTES>>>(z2, W3, b3, out, BATCH, YDIMv, H2v);
}

// round 7
// speedup vs baseline: 1.4659x; 1.1741x over previous
#include <cuda_runtime.h>
#include <cuda_bf16.h>
#include <cstdint>

// ---------------- problem constants ----------------
#define BATCH 512
#define NEQv  4096
#define XDIMv 6144
#define H1v   2048
#define H2v   2048
#define YDIMv 4096
#define NEDGE 32768

// ---------------- scratch (device globals; no runtime alloc) ----------------
__device__ __align__(256) float g_z0[BATCH * XDIMv];
__device__ __align__(256) float g_z1[BATCH * H1v];
__device__ __align__(256) float g_z2[BATCH * H2v];
__device__ __align__(256) __nv_bfloat16 g_w1h[XDIMv * H1v];
__device__ __align__(256) __nv_bfloat16 g_w1l[XDIMv * H1v];
__device__ __align__(256) __nv_bfloat16 g_w2h[H1v * H2v];
__device__ __align__(256) __nv_bfloat16 g_w2l[H1v * H2v];
__device__ __align__(256) __nv_bfloat16 g_w3h[H2v * YDIMv];
__device__ __align__(256) __nv_bfloat16 g_w3l[H2v * YDIMv];
__device__ int   g_cnt[NEQv];
__device__ float g_acc[NEQv];

// ============================================================
// GCN kernels (verified)
// ============================================================
__global__ void k_init() {
    int i = blockIdx.x * blockDim.x + threadIdx.x;
    if (i < NEQv) { g_cnt[i] = 0; g_acc[i] = 0.f; }
}
__global__ void k_count(const int* __restrict__ ei) {
    int e = blockIdx.x * blockDim.x + threadIdx.x;
    if (e < NEDGE) atomicAdd(&g_cnt[ei[NEDGE + e]], 1);
}
__global__ void k_scatter(const int* __restrict__ ei, const float* __restrict__ x,
                          const float* __restrict__ gw) {
    int e = blockIdx.x * blockDim.x + threadIdx.x;
    if (e >= NEDGE) return;
    int s = ei[e];
    int d = ei[NEDGE + e];
    float deg_s = 1.f + 512.f * (float)g_cnt[s];
    float xw = gw[0] * x[(size_t)(s & 511) * XDIMv + (s >> 9)];
    atomicAdd(&g_acc[d], rsqrtf(deg_s) * xw);
}
__global__ void k_build_z(const float* __restrict__ x, const float* __restrict__ gw,
                          const float* __restrict__ gb) {
    int idx = blockIdx.x * blockDim.x + threadIdx.x;
    if (idx >= BATCH * XDIMv) return;
    int b = idx / XDIMv;
    int j = idx - b * XDIMv;
    float v = x[idx];
    float z;
    if (j >= NEQv) {
        z = v;
    } else {
        float xw = gw[0] * v;
        float out;
        if (j < 8) {
            int i = (j << 9) + b;
            float deg = 1.f + 512.f * (float)g_cnt[i];
            out = xw / deg + 512.f * rsqrtf(deg) * g_acc[i] + gb[0];
        } else {
            out = xw + gb[0];
        }
        z = fmaxf(out, 0.f);
    }
    g_z0[idx] = z;
}

// ============================================================
// weight split (elementwise, natural [K,N] layout):
//   Wh = trunc-bf16(W)  (top 16 bits),  Wl = rn-bf16(W - Wh)
// bit-identical to the in-loop packsplit of R6.
// ============================================================
__global__ void k_wsplit(const float* __restrict__ W, __nv_bfloat16* __restrict__ Wh,
                         __nv_bfloat16* __restrict__ Wl, int n4) {
    int i = blockIdx.x * blockDim.x + threadIdx.x;
    if (i >= n4) return;
    float4 v = ((const float4*)W)[i];
    uint32_t u0 = __float_as_uint(v.x), u1 = __float_as_uint(v.y);
    uint32_t u2 = __float_as_uint(v.z), u3 = __float_as_uint(v.w);
    uint2 h;
    h.x = __byte_perm(u0, u1, 0x7632);
    h.y = __byte_perm(u2, u3, 0x7632);
    float l0 = v.x - __uint_as_float(u0 & 0xFFFF0000u);
    float l1 = v.y - __uint_as_float(u1 & 0xFFFF0000u);
    float l2 = v.z - __uint_as_float(u2 & 0xFFFF0000u);
    float l3 = v.w - __uint_as_float(u3 & 0xFFFF0000u);
    __nv_bfloat162 p0 = __floats2bfloat162_rn(l0, l1);
    __nv_bfloat162 p1 = __floats2bfloat162_rn(l2, l3);
    uint2 l; l.x = *(uint32_t*)&p0; l.y = *(uint32_t*)&p1;
    ((uint2*)Wh)[i] = h;
    ((uint2*)Wl)[i] = l;
}

// ============================================================
// GEMM: C[M,N] = act(A[M,K] @ W[K,N] + bias)
// A: fp32 global -> fp32 smem -> in-register packsplit (R6-proven path)
// B: pre-split bf16 Wh/Wl [K,N] -> bf16 smem -> LDS.16 + merge fragments
// mma.m16n8k16.bf16, 3-term split accumulate.
// ============================================================
#define BM 128
#define BN 64
#define BK 32
#define APITCH 40                  // fp32 per A smem row
#define BPITCH 72                  // bf16 per B smem row (144 B)
#define A_BYTES (BM * APITCH * 4)  // 20480
#define B_BYTES (BK * BPITCH * 2)  //  4608 per half
#define STAGE_BYTES (A_BYTES + 2 * B_BYTES)   // 29696
#define STAGES 3
#define GEMM_SMEM_BYTES (STAGES * STAGE_BYTES) // 89088

__device__ __forceinline__ unsigned smem_u32(const void* p) {
    return (unsigned)__cvta_generic_to_shared(p);
}
__device__ __forceinline__ void cp16(void* dst, const void* src) {
    asm volatile("cp.async.ca.shared.global [%0], [%1], 16;\n"
                 :: "r"(smem_u32(dst)), "l"(src));
}
#define CP_COMMIT() asm volatile("cp.async.commit_group;\n")
#define CP_WAIT1()  asm volatile("cp.async.wait_group 1;\n")

#define MMA_BF16(C, A, B)                                                        \
    asm volatile("mma.sync.aligned.m16n8k16.row.col.f32.bf16.bf16.f32 "          \
                 "{%0,%1,%2,%3},{%4,%5,%6,%7},{%8,%9},{%0,%1,%2,%3};\n"          \
                 : "+f"((C)[0]), "+f"((C)[1]), "+f"((C)[2]), "+f"((C)[3])         \
                 : "r"((A)[0]), "r"((A)[1]), "r"((A)[2]), "r"((A)[3]),            \
                   "r"((B)[0]), "r"((B)[1]))

__device__ __forceinline__ void packsplit(float f0, float f1, uint32_t& hi, uint32_t& lo) {
    uint32_t u0 = __float_as_uint(f0), u1 = __float_as_uint(f1);
    hi = __byte_perm(u0, u1, 0x7632);
    float l0 = f0 - __uint_as_float(u0 & 0xFFFF0000u);
    float l1 = f1 - __uint_as_float(u1 & 0xFFFF0000u);
    __nv_bfloat162 p = __floats2bfloat162_rn(l0, l1);
    lo = *(uint32_t*)&p;
}
__device__ __forceinline__ uint32_t merge16(uint32_t lo16, uint32_t hi16) {
    return lo16 | (hi16 << 16);
}

template<int RELU>
__global__ void __launch_bounds__(256, 2) k_gemm(
    const float* __restrict__ A,
    const __nv_bfloat16* __restrict__ Wh, const __nv_bfloat16* __restrict__ Wl,
    const float* __restrict__ bias, float* __restrict__ C,
    int M, int N, int K)
{
    extern __shared__ char smem[];
    const int tid  = threadIdx.x;
    const int lane = tid & 31;
    const int wid  = tid >> 5;
    const int wm   = wid & 3;        // 4 warps in M -> 32 rows each
    const int wn   = wid >> 2;       // 2 warps in N -> 32 cols each
    const int m0   = blockIdx.y * BM;
    const int n0   = blockIdx.x * BN;
    const int r    = lane >> 2;      // 0..7
    const int q    = lane & 3;       // 0..3

    float c[2][4][4];
#pragma unroll
    for (int i = 0; i < 2; i++)
#pragma unroll
        for (int j = 0; j < 4; j++)
#pragma unroll
            for (int k = 0; k < 4; k++) c[i][j][k] = 0.f;

    const int kIters = K / BK;

    auto loadStage = [&](int it, int stg) {
        const int k0 = it * BK;
        char* st = smem + stg * STAGE_BYTES;
        // A: 128 rows x 8 chunks of 16B (fp32)
        float* as = (float*)st;
#pragma unroll
        for (int t = 0; t < 4; t++) {
            int id = tid + t * 256;
            int rr = id >> 3, ch = (id & 7) << 2;
            cp16(&as[rr * APITCH + ch], &A[(size_t)(m0 + rr) * K + k0 + ch]);
        }
        // B: 2 halves x 32 rows x 8 chunks of 16B (bf16)
#pragma unroll
        for (int t = 0; t < 2; t++) {
            int id = tid + t * 256;          // 0..511
            int a  = id >> 8;                // 0=h, 1=l
            int rb = id & 255;
            int rr = rb >> 3, ch = rb & 7;
            const __nv_bfloat16* src = (a ? Wl : Wh) + (size_t)(k0 + rr) * N + n0 + ch * 8;
            cp16(st + A_BYTES + a * B_BYTES + rr * (BPITCH * 2) + ch * 16, src);
        }
    };

    loadStage(0, 0); CP_COMMIT();
    loadStage(1, 1); CP_COMMIT();

    for (int it = 0; it < kIters; ++it) {
        CP_WAIT1();
        __syncthreads();
        if (it + 2 < kIters) loadStage(it + 2, (it + 2) % STAGES);
        CP_COMMIT();

        const char* st  = smem + (it % STAGES) * STAGE_BYTES;
        const float* as = (const float*)st;
        const char* sBh = st + A_BYTES;
        const char* sBl = st + A_BYTES + B_BYTES;

#pragma unroll
        for (int kk = 0; kk < BK; kk += 16) {
            uint32_t ah[2][4], al[2][4], bh[4][2], bl[4][2];
#pragma unroll
            for (int mt = 0; mt < 2; mt++) {
                const float* ap = &as[(wm * 32 + mt * 16 + r) * APITCH + kk + 2 * q];
                float2 p0 = *(const float2*)(ap);
                float2 p1 = *(const float2*)(ap + 8 * APITCH);
                float2 p2 = *(const float2*)(ap + 8);
                float2 p3 = *(const float2*)(ap + 8 * APITCH + 8);
                packsplit(p0.x, p0.y, ah[mt][0], al[mt][0]);
                packsplit(p1.x, p1.y, ah[mt][1], al[mt][1]);
                packsplit(p2.x, p2.y, ah[mt][2], al[mt][2]);
                packsplit(p3.x, p3.y, ah[mt][3], al[mt][3]);
            }
#pragma unroll
            for (int nt = 0; nt < 4; nt++) {
                const int n  = wn * 32 + nt * 8 + r;
                const int kb = (kk + 2 * q) * (BPITCH * 2) + n * 2;   // byte offset
                uint32_t h00 = *(const uint16_t*)(sBh + kb);
                uint32_t h01 = *(const uint16_t*)(sBh + kb + BPITCH * 2);
                uint32_t h10 = *(const uint16_t*)(sBh + kb + 8 * BPITCH * 2);
                uint32_t h11 = *(const uint16_t*)(sBh + kb + 9 * BPITCH * 2);
                bh[nt][0] = merge16(h00, h01);
                bh[nt][1] = merge16(h10, h11);
                uint32_t l00 = *(const uint16_t*)(sBl + kb);
                uint32_t l01 = *(const uint16_t*)(sBl + kb + BPITCH * 2);
                uint32_t l10 = *(const uint16_t*)(sBl + kb + 8 * BPITCH * 2);
                uint32_t l11 = *(const uint16_t*)(sBl + kb + 9 * BPITCH * 2);
                bl[nt][0] = merge16(l00, l01);
                bl[nt][1] = merge16(l10, l11);
            }
            // 3 split terms; each sweep = 8 independent accumulators (ILP)
#pragma unroll
            for (int mt = 0; mt < 2; mt++)
#pragma unroll
                for (int nt = 0; nt < 4; nt++)
                    MMA_BF16(c[mt][nt], ah[mt], bh[nt]);
#pragma unroll
            for (int mt = 0; mt < 2; mt++)
#pragma unroll
                for (int nt = 0; nt < 4; nt++)
                    MMA_BF16(c[mt][nt], ah[mt], bl[nt]);
#pragma unroll
            for (int mt = 0; mt < 2; mt++)
#pragma unroll
                for (int nt = 0; nt < 4; nt++)
                    MMA_BF16(c[mt][nt], al[mt], bh[nt]);
        }
    }

    // epilogue: bias + optional relu (R6-proven)
#pragma unroll
    for (int mt = 0; mt < 2; mt++) {
#pragma unroll
        for (int nt = 0; nt < 4; nt++) {
            int row0 = m0 + wm * 32 + mt * 16 + r;
            int col0 = n0 + wn * 32 + nt * 8 + 2 * q;
            float bb0 = bias[col0], bb1 = bias[col0 + 1];
            float2 v0 = make_float2(c[mt][nt][0] + bb0, c[mt][nt][1] + bb1);
            float2 v1 = make_float2(c[mt][nt][2] + bb0, c[mt][nt][3] + bb1);
            if (RELU) {
                v0.x = fmaxf(v0.x, 0.f); v0.y = fmaxf(v0.y, 0.f);
                v1.x = fmaxf(v1.x, 0.f); v1.y = fmaxf(v1.y, 0.f);
            }
            *(float2*)&C[(size_t)row0 * N + col0]       = v0;
            *(float2*)&C[(size_t)(row0 + 8) * N + col0] = v1;
        }
    }
}

// ============================================================
// launch
// ============================================================
extern "C" void kernel_launch(void* const* d_in, const int* in_sizes, int n_in,
                              void* d_out, int out_size) {
    const float* x  = (const float*)d_in[0];
    const int*   ei = (const int*)  d_in[1];
    const float* gw = (const float*)d_in[2];
    const float* gb = (const float*)d_in[3];
    const float* W1 = (const float*)d_in[4];
    const float* b1 = (const float*)d_in[5];
    const float* W2 = (const float*)d_in[6];
    const float* b2 = (const float*)d_in[7];
    const float* W3 = (const float*)d_in[8];
    const float* b3 = (const float*)d_in[9];
    float* out = (float*)d_out;

    cudaFuncSetAttribute(k_gemm<1>, cudaFuncAttributeMaxDynamicSharedMemorySize, GEMM_SMEM_BYTES);
    cudaFuncSetAttribute(k_gemm<0>, cudaFuncAttributeMaxDynamicSharedMemorySize, GEMM_SMEM_BYTES);

    void *z0p, *z1p, *z2p, *w1hp, *w1lp, *w2hp, *w2lp, *w3hp, *w3lp;
    cudaGetSymbolAddress(&z0p, g_z0);
    cudaGetSymbolAddress(&z1p, g_z1);
    cudaGetSymbolAddress(&z2p, g_z2);
    cudaGetSymbolAddress(&w1hp, g_w1h); cudaGetSymbolAddress(&w1lp, g_w1l);
    cudaGetSymbolAddress(&w2hp, g_w2h); cudaGetSymbolAddress(&w2lp, g_w2l);
    cudaGetSymbolAddress(&w3hp, g_w3h); cudaGetSymbolAddress(&w3lp, g_w3l);
    float* z0 = (float*)z0p;
    float* z1 = (float*)z1p;
    float* z2 = (float*)z2p;

    // weight splits (independent of GCN)
    k_wsplit<<<(XDIMv * H1v / 4 + 255) / 256, 256>>>(W1, (__nv_bfloat16*)w1hp, (__nv_bfloat16*)w1lp, XDIMv * H1v / 4);
    k_wsplit<<<(H1v * H2v / 4 + 255) / 256, 256>>>(W2, (__nv_bfloat16*)w2hp, (__nv_bfloat16*)w2lp, H1v * H2v / 4);
    k_wsplit<<<(H2v * YDIMv / 4 + 255) / 256, 256>>>(W3, (__nv_bfloat16*)w3hp, (__nv_bfloat16*)w3lp, H2v * YDIMv / 4);

    // GCN
    k_init<<<NEQv / 256, 256>>>();
    k_count<<<NEDGE / 256, 256>>>(ei);
    k_scatter<<<NEDGE / 256, 256>>>(ei, x, gw);
    k_build_z<<<(BATCH * XDIMv) / 256, 256>>>(x, gw, gb);

    // MLP
    dim3 g1(H1v / BN,   BATCH / BM);
    dim3 g2(H2v / BN,   BATCH / BM);
    dim3 g3(YDIMv / BN, BATCH / BM);
    k_gemm<1><<<g1, 256, GEMM_SMEM_BYTES>>>(z0, (const __nv_bfloat16*)w1hp, (const __nv_bfloat16*)w1lp, b1, z1, BATCH, H1v,   XDIMv);
    k_gemm<1><<<g2, 256, GEMM_SMEM_BYTES>>>(z1, (const __nv_bfloat16*)w2hp, (const __nv_bfloat16*)w2lp, b2, z2, BATCH, H2v,   H1v);
    k_gemm<0><<<g3, 256, GEMM_SMEM_BYTES>>>(z2, (const __nv_bfloat16*)w3hp, (const __nv_bfloat16*)w3lp, b3, out, BATCH, YDIMv, H2v);
}